// round 1
// baseline (speedup 1.0000x reference)
#include <cuda_runtime.h>
#include <cstdint>

#define N_NODES 20000
#define N_EDGES 320000
#define TPW 4  // edges per warp per iteration

// Scratch (device globals — no allocation allowed)
__device__ float g_sup[N_NODES * 64];    // up-projected scalars  [n][u]
__device__ float g_vup[N_NODES * 192];   // up-projected vectors  [n][u][m]
__device__ float g_msgs[N_NODES * 128];  // scalar messages       [n][u]   (m_s0 | m_s1)
__device__ float g_msgv[N_NODES * 384];  // vector messages       [n][m][p] (p<64: v0, p>=64: v1)

__device__ __forceinline__ float silu_f(float x) {
    return __fdividef(x, 1.0f + __expf(-x));
}

// ---------------------------------------------------------------------------
// Zero the message accumulators
// ---------------------------------------------------------------------------
__global__ void zero_kernel() {
    int idx = blockIdx.x * blockDim.x + threadIdx.x;
    int stride = gridDim.x * blockDim.x;
    const int ns = N_NODES * 128 / 4;
    const int nv = N_NODES * 384 / 4;
    float4 z = make_float4(0.f, 0.f, 0.f, 0.f);
    for (int i = idx; i < ns; i += stride) ((float4*)g_msgs)[i] = z;
    for (int i = idx; i < nv; i += stride) ((float4*)g_msgv)[i] = z;
}

// ---------------------------------------------------------------------------
// Node up-projection: s' = s @ W_up0 / 8 ; v' = einsum(num,uv->nvm) / 8
// ---------------------------------------------------------------------------
__global__ __launch_bounds__(256) void nodeup_kernel(
    const float* __restrict__ nf, const float* __restrict__ W0,
    const float* __restrict__ W1) {
    __shared__ float sW0[4096], sW1[4096], sx[1024];
    int tid = threadIdx.x;
    for (int i = tid; i < 4096; i += 256) { sW0[i] = W0[i]; sW1[i] = W1[i]; }
    int ln = tid >> 6, c = tid & 63;
    for (int nb = blockIdx.x * 4; nb < N_NODES; nb += gridDim.x * 4) {
        __syncthreads();
        for (int i = tid; i < 1024; i += 256) {
            int nn = nb + (i >> 8);
            sx[i] = (nn < N_NODES) ? nf[(size_t)nn * 256 + (i & 255)] : 0.f;
        }
        __syncthreads();
        int n = nb + ln;
        if (n < N_NODES) {
            const float* x = sx + (ln << 8);
            float as = 0.f, a0 = 0.f, a1 = 0.f, a2 = 0.f;
#pragma unroll 8
            for (int u = 0; u < 64; u++) {
                float w0 = sW0[u * 64 + c], w1 = sW1[u * 64 + c];
                as += x[u] * w0;
                a0 += x[64 + 3 * u]     * w1;
                a1 += x[64 + 3 * u + 1] * w1;
                a2 += x[64 + 3 * u + 2] * w1;
            }
            g_sup[(size_t)n * 64 + c] = as * 0.125f;
            float* vp = g_vup + (size_t)n * 192 + 3 * c;
            vp[0] = a0 * 0.125f; vp[1] = a1 * 0.125f; vp[2] = a2 * 0.125f;
        }
    }
}

// ---------------------------------------------------------------------------
// Fused edge kernel: MLP(8->64->64->64->256) -> message build -> atomic scatter
// One warp processes TPW=4 edges per pass, all MLP weights in shared memory.
// ---------------------------------------------------------------------------
#define EDGE_SMEM ((512 + 4096 + 4096 + 16384 + 8 * TPW * 64) * 4)

__global__ __launch_bounds__(256, 2) void edge_kernel(
    const float* __restrict__ edge_attrs, const float* __restrict__ edge_feats,
    const int* __restrict__ snd_idx, const int* __restrict__ rcv_idx,
    const float* __restrict__ M1, const float* __restrict__ M2,
    const float* __restrict__ M3, const float* __restrict__ M4) {
    extern __shared__ float smem[];
    float* sM1 = smem;
    float* sM2 = sM1 + 512;
    float* sM3 = sM2 + 4096;
    float* sM4 = sM3 + 4096;
    float* sh  = sM4 + 16384;
    int tid = threadIdx.x;
    for (int i = tid; i < 512;  i += 256) sM1[i] = M1[i];
    for (int i = tid; i < 4096; i += 256) { sM2[i] = M2[i]; sM3[i] = M3[i]; }
    for (int i = tid; i < 16384; i += 256) sM4[i] = M4[i];
    __syncthreads();

    int warp = tid >> 5, lane = tid & 31;
    float* hh = sh + warp * (TPW * 64);
    const int ngroups = N_EDGES / TPW;
    const float INV_SQRT3 = 0.57735026918962576f;
    const float S1 = 0.35355339059327379f;  // 1/sqrt(8)

    for (int g = blockIdx.x * 8 + warp; g < ngroups; g += gridDim.x * 8) {
        int e0 = g * TPW;
        // ---- layer 1 : ef(8) @ M1 -> h(64), silu ----
        float ef[TPW][8];
#pragma unroll
        for (int t = 0; t < TPW; t++) {
            const float4* p = (const float4*)(edge_feats + (size_t)(e0 + t) * 8);
            float4 A = __ldg(p), B = __ldg(p + 1);
            ef[t][0] = A.x; ef[t][1] = A.y; ef[t][2] = A.z; ef[t][3] = A.w;
            ef[t][4] = B.x; ef[t][5] = B.y; ef[t][6] = B.z; ef[t][7] = B.w;
        }
        float acc[TPW][2];
#pragma unroll
        for (int t = 0; t < TPW; t++) { acc[t][0] = 0.f; acc[t][1] = 0.f; }
#pragma unroll
        for (int i = 0; i < 8; i++) {
            float2 w = *(const float2*)&sM1[i * 64 + 2 * lane];
#pragma unroll
            for (int t = 0; t < TPW; t++) {
                acc[t][0] += ef[t][i] * w.x;
                acc[t][1] += ef[t][i] * w.y;
            }
        }
#pragma unroll
        for (int t = 0; t < TPW; t++) {
            float2 hv;
            hv.x = silu_f(acc[t][0] * S1);
            hv.y = silu_f(acc[t][1] * S1);
            *(float2*)&hh[t * 64 + 2 * lane] = hv;
        }
        __syncwarp();

        // ---- layers 2 & 3 : h @ M -> h, silu, scale 1/8 ----
#pragma unroll
        for (int L = 0; L < 2; L++) {
            const float* W = (L == 0) ? sM2 : sM3;
#pragma unroll
            for (int t = 0; t < TPW; t++) { acc[t][0] = 0.f; acc[t][1] = 0.f; }
            for (int i = 0; i < 64; i += 4) {
                float ha[TPW][4];
#pragma unroll
                for (int t = 0; t < TPW; t++) {
                    float4 q = *(const float4*)&hh[t * 64 + i];
                    ha[t][0] = q.x; ha[t][1] = q.y; ha[t][2] = q.z; ha[t][3] = q.w;
                }
#pragma unroll
                for (int k = 0; k < 4; k++) {
                    float2 w = *(const float2*)&W[(i + k) * 64 + 2 * lane];
#pragma unroll
                    for (int t = 0; t < TPW; t++) {
                        acc[t][0] += ha[t][k] * w.x;
                        acc[t][1] += ha[t][k] * w.y;
                    }
                }
            }
            __syncwarp();
#pragma unroll
            for (int t = 0; t < TPW; t++) {
                float2 hv;
                hv.x = silu_f(acc[t][0] * 0.125f);
                hv.y = silu_f(acc[t][1] * 0.125f);
                *(float2*)&hh[t * 64 + 2 * lane] = hv;
            }
            __syncwarp();
        }

        // ---- layer 4 : h @ M4 -> tpw(256), scale 1/8 (no silu) ----
        // a4[t][j] = tpw[32*j + lane]
        float a4[TPW][8];
#pragma unroll
        for (int t = 0; t < TPW; t++)
#pragma unroll
            for (int j = 0; j < 8; j++) a4[t][j] = 0.f;
        for (int i = 0; i < 64; i += 4) {
            float ha[TPW][4];
#pragma unroll
            for (int t = 0; t < TPW; t++) {
                float4 q = *(const float4*)&hh[t * 64 + i];
                ha[t][0] = q.x; ha[t][1] = q.y; ha[t][2] = q.z; ha[t][3] = q.w;
            }
#pragma unroll
            for (int k = 0; k < 4; k++) {
                const float* wr = &sM4[(i + k) * 256 + lane];
#pragma unroll
                for (int j = 0; j < 8; j++) {
                    float w = wr[32 * j];
#pragma unroll
                    for (int t = 0; t < TPW; t++) a4[t][j] += ha[t][k] * w;
                }
            }
        }
#pragma unroll
        for (int t = 0; t < TPW; t++)
#pragma unroll
            for (int j = 0; j < 8; j++) a4[t][j] *= 0.125f;

        // ---- message construction + scatter ----
#pragma unroll
        for (int t = 0; t < TPW; t++) {
            int e = e0 + t;
            int snd = __ldg(&snd_idx[e]);
            int rcv = __ldg(&rcv_idx[e]);
            float4 ea = __ldg((const float4*)(edge_attrs + (size_t)e * 4));
            float ys = ea.x, yv0 = ea.y, yv1 = ea.z, yv2 = ea.w;
            const float* sup = g_sup + (size_t)snd * 64;
            const float* vup = g_vup + (size_t)snd * 192;
            float* ms = g_msgs + (size_t)rcv * 128;
            float* mv = g_msgv + (size_t)rcv * 384;
#pragma unroll
            for (int j = 0; j < 2; j++) {
                int u = lane + 32 * j;
                float xs  = __ldg(sup + u);
                float xv0 = __ldg(vup + 3 * u);
                float xv1 = __ldg(vup + 3 * u + 1);
                float xv2 = __ldg(vup + 3 * u + 2);
                float w0 = a4[t][0 + j], w1 = a4[t][2 + j];
                float w2 = a4[t][4 + j], w3 = a4[t][6 + j];
                float dv = xv0 * yv0 + xv1 * yv1 + xv2 * yv2;
                atomicAdd(ms + u,       w0 * xs * ys);
                atomicAdd(ms + 64 + u,  w3 * dv * INV_SQRT3);
                float wxs = w1 * xs;
                atomicAdd(mv + u,        wxs * yv0);
                atomicAdd(mv + 128 + u,  wxs * yv1);
                atomicAdd(mv + 256 + u,  wxs * yv2);
                float wys = w2 * ys;
                atomicAdd(mv + 64 + u,        wys * xv0);
                atomicAdd(mv + 128 + 64 + u,  wys * xv1);
                atomicAdd(mv + 256 + 64 + u,  wys * xv2);
            }
        }
    }
}

// ---------------------------------------------------------------------------
// Node output: out_s = S @ W_lin0 * sc ; out_v = einsum(num,uv->nvm) * sc
// ---------------------------------------------------------------------------
#define NODEOUT_SMEM ((8192 + 8192 + 512 + 1536) * 4)

__global__ __launch_bounds__(256) void nodeout_kernel(
    const float* __restrict__ WL0, const float* __restrict__ WL1,
    float* __restrict__ out) {
    extern __shared__ float smem[];
    float* sW0 = smem;          // 128x64
    float* sW1 = sW0 + 8192;    // 128x64
    float* sms = sW1 + 8192;    // 4 x 128
    float* smv = sms + 512;     // 4 x 384
    int tid = threadIdx.x;
    for (int i = tid; i < 8192; i += 256) { sW0[i] = WL0[i]; sW1[i] = WL1[i]; }
    int ln = tid >> 6, c = tid & 63;
    const float SC = 0.0055242717280199021f;  // 1/(sqrt(128)*16)
    for (int nb = blockIdx.x * 4; nb < N_NODES; nb += gridDim.x * 4) {
        __syncthreads();
        for (int i = tid; i < 512; i += 256) {
            int nn = nb + (i >> 7);
            sms[i] = (nn < N_NODES) ? g_msgs[(size_t)nn * 128 + (i & 127)] : 0.f;
        }
        for (int i = tid; i < 1536; i += 256) {
            int nn = nb + i / 384;
            smv[i] = (nn < N_NODES) ? g_msgv[(size_t)nn * 384 + i % 384] : 0.f;
        }
        __syncthreads();
        int n = nb + ln;
        if (n < N_NODES) {
            const float* S = sms + ln * 128;
            const float* V = smv + ln * 384;
            float as = 0.f, a0 = 0.f, a1 = 0.f, a2 = 0.f;
#pragma unroll 4
            for (int u = 0; u < 128; u++) {
                float w0 = sW0[u * 64 + c], w1 = sW1[u * 64 + c];
                as += S[u] * w0;
                a0 += V[u] * w1;
                a1 += V[128 + u] * w1;
                a2 += V[256 + u] * w1;
            }
            float* o = out + (size_t)n * 256;
            o[c] = as * SC;
            o[64 + 3 * c]     = a0 * SC;
            o[64 + 3 * c + 1] = a1 * SC;
            o[64 + 3 * c + 2] = a2 * SC;
        }
    }
}

// ---------------------------------------------------------------------------
extern "C" void kernel_launch(void* const* d_in, const int* in_sizes, int n_in,
                              void* d_out, int out_size) {
    // metadata order: node_attrs, node_feats, edge_attrs, edge_feats,
    // edge_index, W_up0, W_up1, M1, M2, M3, M4, W_lin0, W_lin1, W_skip0, W_skip1
    const float* node_feats = (const float*)d_in[1];
    const float* edge_attrs = (const float*)d_in[2];
    const float* edge_feats = (const float*)d_in[3];
    const int*   eidx       = (const int*)d_in[4];
    const float* W_up0      = (const float*)d_in[5];
    const float* W_up1      = (const float*)d_in[6];
    const float* M1         = (const float*)d_in[7];
    const float* M2         = (const float*)d_in[8];
    const float* M3         = (const float*)d_in[9];
    const float* M4         = (const float*)d_in[10];
    const float* WL0        = (const float*)d_in[11];
    const float* WL1        = (const float*)d_in[12];
    float* out = (float*)d_out;

    cudaFuncSetAttribute(edge_kernel,
                         cudaFuncAttributeMaxDynamicSharedMemorySize, EDGE_SMEM);
    cudaFuncSetAttribute(nodeout_kernel,
                         cudaFuncAttributeMaxDynamicSharedMemorySize, NODEOUT_SMEM);

    zero_kernel<<<256, 256>>>();
    nodeup_kernel<<<592, 256>>>(node_feats, W_up0, W_up1);
    edge_kernel<<<296, 256, EDGE_SMEM>>>(edge_attrs, edge_feats,
                                         eidx, eidx + N_EDGES, M1, M2, M3, M4);
    nodeout_kernel<<<444, 256, NODEOUT_SMEM>>>(WL0, WL1, out);
}

// round 2
// speedup vs baseline: 1.1940x; 1.1940x over previous
#include <cuda_runtime.h>
#include <cstdint>

#define N_NODES 20000
#define N_EDGES 320000
#define TPW 4  // edges per warp per iteration

typedef unsigned long long ull;

// Scratch (device globals — no allocation allowed)
__device__ float g_sup[N_NODES * 64];    // up-projected scalars  [n][u]
__device__ float g_vup[N_NODES * 192];   // up-projected vectors  [n][u][m]
__device__ float g_msgs[N_NODES * 128];  // scalar messages       [n][u]   (m_s0 | m_s1)
__device__ float g_msgv[N_NODES * 384];  // vector messages       [n][m][p] (p<64: v0, p>=64: v1)

__device__ __forceinline__ float silu_f(float x) {
    return __fdividef(x, 1.0f + __expf(-x));
}

// ---- packed f32x2 helpers (sm_103a) ----
__device__ __forceinline__ ull pack2(float x, float y) {
    ull d; asm("mov.b64 %0, {%1, %2};" : "=l"(d) : "f"(x), "f"(y)); return d;
}
__device__ __forceinline__ void unpack2(ull v, float& x, float& y) {
    asm("mov.b64 {%0, %1}, %2;" : "=f"(x), "=f"(y) : "l"(v));
}
__device__ __forceinline__ ull fma2(ull a, ull b, ull c) {
    ull d; asm("fma.rn.f32x2 %0, %1, %2, %3;" : "=l"(d) : "l"(a), "l"(b), "l"(c)); return d;
}

// ---------------------------------------------------------------------------
// Zero the message accumulators
// ---------------------------------------------------------------------------
__global__ void zero_kernel() {
    int idx = blockIdx.x * blockDim.x + threadIdx.x;
    int stride = gridDim.x * blockDim.x;
    const int ns = N_NODES * 128 / 4;
    const int nv = N_NODES * 384 / 4;
    float4 z = make_float4(0.f, 0.f, 0.f, 0.f);
    for (int i = idx; i < ns; i += stride) ((float4*)g_msgs)[i] = z;
    for (int i = idx; i < nv; i += stride) ((float4*)g_msgv)[i] = z;
}

// ---------------------------------------------------------------------------
// Node up-projection: s' = s @ W_up0 / 8 ; v' = einsum(num,uv->nvm) / 8
// 16 nodes per tile; thread = (local node, 4-col group); LDS.128 weights.
// ---------------------------------------------------------------------------
#define NUP_SMEM ((4096 + 4096 + 16 * 256) * 4)

__global__ __launch_bounds__(256) void nodeup_kernel(
    const float* __restrict__ nf, const float* __restrict__ W0,
    const float* __restrict__ W1) {
    extern __shared__ float smem[];
    float* sW0 = smem;            // 64x64
    float* sW1 = sW0 + 4096;      // 64x64
    float* sx  = sW1 + 4096;      // 16 x 256
    int tid = threadIdx.x;
    for (int i = tid; i < 4096; i += 256) { sW0[i] = W0[i] * 0.125f; sW1[i] = W1[i] * 0.125f; }
    int ln = tid >> 4;          // local node 0..15
    int cg = tid & 15;          // col group (4 cols)
    const float4* w0v = (const float4*)sW0;
    const float4* w1v = (const float4*)sW1;
    const int ntiles = N_NODES / 16;
    for (int tile = blockIdx.x; tile < ntiles; tile += gridDim.x) {
        int nb = tile * 16;
        __syncthreads();
        {
            const float4* src = (const float4*)(nf + (size_t)nb * 256);
            float4* dst = (float4*)sx;
            for (int i = tid; i < 1024; i += 256) dst[i] = src[i];
        }
        __syncthreads();
        const float* x = sx + ln * 256;
        float4 aS = make_float4(0.f, 0.f, 0.f, 0.f);
        float4 a0 = aS, a1 = aS, a2 = aS;
#pragma unroll 4
        for (int u = 0; u < 64; u++) {
            float4 w0 = w0v[u * 16 + cg];
            float4 w1 = w1v[u * 16 + cg];
            float s  = x[u];
            float v0 = x[64 + 3 * u], v1 = x[64 + 3 * u + 1], v2 = x[64 + 3 * u + 2];
            aS.x += s * w0.x; aS.y += s * w0.y; aS.z += s * w0.z; aS.w += s * w0.w;
            a0.x += v0 * w1.x; a0.y += v0 * w1.y; a0.z += v0 * w1.z; a0.w += v0 * w1.w;
            a1.x += v1 * w1.x; a1.y += v1 * w1.y; a1.z += v1 * w1.z; a1.w += v1 * w1.w;
            a2.x += v2 * w1.x; a2.y += v2 * w1.y; a2.z += v2 * w1.z; a2.w += v2 * w1.w;
        }
        int n = nb + ln;
        *(float4*)(g_sup + (size_t)n * 64 + 4 * cg) = aS;
        float* vp = g_vup + (size_t)n * 192 + 12 * cg;
        ((float4*)vp)[0] = make_float4(a0.x, a1.x, a2.x, a0.y);
        ((float4*)vp)[1] = make_float4(a1.y, a2.y, a0.z, a1.z);
        ((float4*)vp)[2] = make_float4(a2.z, a0.w, a1.w, a2.w);
    }
}

// ---------------------------------------------------------------------------
// Fused edge kernel: MLP(8->64->64->64->256) -> message build -> atomic scatter
// One warp processes TPW=4 edges per pass, all MLP weights in shared memory.
// Layer 4 uses packed f32x2 FMA with a pair-permuted M4 layout.
// ---------------------------------------------------------------------------
#define EDGE_SMEM ((512 + 4096 + 4096 + 16384 + 8 * TPW * 64) * 4)

__global__ __launch_bounds__(256, 2) void edge_kernel(
    const float* __restrict__ edge_attrs, const float* __restrict__ edge_feats,
    const int* __restrict__ snd_idx, const int* __restrict__ rcv_idx,
    const float* __restrict__ M1, const float* __restrict__ M2,
    const float* __restrict__ M3, const float* __restrict__ M4) {
    extern __shared__ float smem[];
    float* sM1 = smem;
    float* sM2 = sM1 + 512;
    float* sM3 = sM2 + 4096;
    float* sM4 = sM3 + 4096;   // pair-permuted, pre-scaled by 1/8
    float* sh  = sM4 + 16384;
    int tid = threadIdx.x;
    for (int i = tid; i < 512;  i += 256) sM1[i] = M1[i];
    for (int i = tid; i < 4096; i += 256) { sM2[i] = M2[i]; sM3[i] = M3[i]; }
    // Permute M4 so that for each row i, the pair (col 32j+l, col 32j+32+l)
    // is stored adjacently: dest = i*256 + (jp*32 + l)*2 + half, j = 2*jp+half.
    for (int idx = tid; idx < 16384; idx += 256) {
        int i = idx >> 8, c = idx & 255;
        int j = c >> 5, lc = c & 31, jp = j >> 1, half = j & 1;
        sM4[(i << 8) + (((jp << 5) + lc) << 1) + half] = M4[idx] * 0.125f;
    }
    __syncthreads();

    int warp = tid >> 5, lane = tid & 31;
    float* hh = sh + warp * (TPW * 64);
    const int ngroups = N_EDGES / TPW;
    const float INV_SQRT3 = 0.57735026918962576f;
    const float S1 = 0.35355339059327379f;  // 1/sqrt(8)

    for (int g = blockIdx.x * 8 + warp; g < ngroups; g += gridDim.x * 8) {
        int e0 = g * TPW;
        // ---- layer 1 : ef(8) @ M1 -> h(64), silu ----
        float ef[TPW][8];
#pragma unroll
        for (int t = 0; t < TPW; t++) {
            const float4* p = (const float4*)(edge_feats + (size_t)(e0 + t) * 8);
            float4 A = __ldg(p), B = __ldg(p + 1);
            ef[t][0] = A.x; ef[t][1] = A.y; ef[t][2] = A.z; ef[t][3] = A.w;
            ef[t][4] = B.x; ef[t][5] = B.y; ef[t][6] = B.z; ef[t][7] = B.w;
        }
        float acc[TPW][2];
#pragma unroll
        for (int t = 0; t < TPW; t++) { acc[t][0] = 0.f; acc[t][1] = 0.f; }
#pragma unroll
        for (int i = 0; i < 8; i++) {
            float2 w = *(const float2*)&sM1[i * 64 + 2 * lane];
#pragma unroll
            for (int t = 0; t < TPW; t++) {
                acc[t][0] += ef[t][i] * w.x;
                acc[t][1] += ef[t][i] * w.y;
            }
        }
#pragma unroll
        for (int t = 0; t < TPW; t++) {
            float2 hv;
            hv.x = silu_f(acc[t][0] * S1);
            hv.y = silu_f(acc[t][1] * S1);
            *(float2*)&hh[t * 64 + 2 * lane] = hv;
        }
        __syncwarp();

        // ---- layers 2 & 3 : h @ M -> h, silu, scale 1/8 ----
#pragma unroll
        for (int L = 0; L < 2; L++) {
            const float* W = (L == 0) ? sM2 : sM3;
#pragma unroll
            for (int t = 0; t < TPW; t++) { acc[t][0] = 0.f; acc[t][1] = 0.f; }
            for (int i = 0; i < 64; i += 4) {
                float ha[TPW][4];
#pragma unroll
                for (int t = 0; t < TPW; t++) {
                    float4 q = *(const float4*)&hh[t * 64 + i];
                    ha[t][0] = q.x; ha[t][1] = q.y; ha[t][2] = q.z; ha[t][3] = q.w;
                }
#pragma unroll
                for (int k = 0; k < 4; k++) {
                    float2 w = *(const float2*)&W[(i + k) * 64 + 2 * lane];
#pragma unroll
                    for (int t = 0; t < TPW; t++) {
                        acc[t][0] += ha[t][k] * w.x;
                        acc[t][1] += ha[t][k] * w.y;
                    }
                }
            }
            __syncwarp();
#pragma unroll
            for (int t = 0; t < TPW; t++) {
                float2 hv;
                hv.x = silu_f(acc[t][0] * 0.125f);
                hv.y = silu_f(acc[t][1] * 0.125f);
                *(float2*)&hh[t * 64 + 2 * lane] = hv;
            }
            __syncwarp();
        }

        // ---- layer 4 : h @ M4 -> tpw(256), packed f32x2 ----
        // a4p[t][jp] holds (tpw[32*(2jp)+lane], tpw[32*(2jp+1)+lane]), scaled 1/8.
        ull a4p[TPW][4];
#pragma unroll
        for (int t = 0; t < TPW; t++)
#pragma unroll
            for (int jp = 0; jp < 4; jp++) a4p[t][jp] = 0ull;
        for (int i = 0; i < 64; i += 4) {
            float ha[TPW][4];
#pragma unroll
            for (int t = 0; t < TPW; t++) {
                float4 q = *(const float4*)&hh[t * 64 + i];
                ha[t][0] = q.x; ha[t][1] = q.y; ha[t][2] = q.z; ha[t][3] = q.w;
            }
#pragma unroll
            for (int k = 0; k < 4; k++) {
                const float* wr = &sM4[((i + k) << 8) + 2 * lane];
                ull wp0 = *(const ull*)(wr);
                ull wp1 = *(const ull*)(wr + 64);
                ull wp2 = *(const ull*)(wr + 128);
                ull wp3 = *(const ull*)(wr + 192);
#pragma unroll
                for (int t = 0; t < TPW; t++) {
                    ull aa = pack2(ha[t][k], ha[t][k]);
                    a4p[t][0] = fma2(aa, wp0, a4p[t][0]);
                    a4p[t][1] = fma2(aa, wp1, a4p[t][1]);
                    a4p[t][2] = fma2(aa, wp2, a4p[t][2]);
                    a4p[t][3] = fma2(aa, wp3, a4p[t][3]);
                }
            }
        }

        // ---- message construction + scatter ----
#pragma unroll
        for (int t = 0; t < TPW; t++) {
            int e = e0 + t;
            int snd = __ldg(&snd_idx[e]);
            int rcv = __ldg(&rcv_idx[e]);
            float4 ea = __ldg((const float4*)(edge_attrs + (size_t)e * 4));
            float ys = ea.x, yv0 = ea.y, yv1 = ea.z, yv2 = ea.w;
            const float* sup = g_sup + (size_t)snd * 64;
            const float* vup = g_vup + (size_t)snd * 192;
            float* ms = g_msgs + (size_t)rcv * 128;
            float* mv = g_msgv + (size_t)rcv * 384;
            float w0a, w0b, w1a, w1b, w2a, w2b, w3a, w3b;
            unpack2(a4p[t][0], w0a, w0b);
            unpack2(a4p[t][1], w1a, w1b);
            unpack2(a4p[t][2], w2a, w2b);
            unpack2(a4p[t][3], w3a, w3b);
#pragma unroll
            for (int j = 0; j < 2; j++) {
                int u = lane + 32 * j;
                float xs  = __ldg(sup + u);
                float xv0 = __ldg(vup + 3 * u);
                float xv1 = __ldg(vup + 3 * u + 1);
                float xv2 = __ldg(vup + 3 * u + 2);
                float w0 = j ? w0b : w0a;
                float w1 = j ? w1b : w1a;
                float w2 = j ? w2b : w2a;
                float w3 = j ? w3b : w3a;
                float dv = xv0 * yv0 + xv1 * yv1 + xv2 * yv2;
                atomicAdd(ms + u,       w0 * xs * ys);
                atomicAdd(ms + 64 + u,  w3 * dv * INV_SQRT3);
                float wxs = w1 * xs;
                atomicAdd(mv + u,        wxs * yv0);
                atomicAdd(mv + 128 + u,  wxs * yv1);
                atomicAdd(mv + 256 + u,  wxs * yv2);
                float wys = w2 * ys;
                atomicAdd(mv + 64 + u,        wys * xv0);
                atomicAdd(mv + 128 + 64 + u,  wys * xv1);
                atomicAdd(mv + 256 + 64 + u,  wys * xv2);
            }
        }
    }
}

// ---------------------------------------------------------------------------
// Node output: out_s = S @ W_lin0 * sc ; out_v = einsum(num,uv->nvm) * sc
// 16 nodes per tile; thread = (local node, 4-col group); LDS.128 weights.
// ---------------------------------------------------------------------------
#define NODEOUT_SMEM ((8192 + 8192 + 16 * 512) * 4)

__global__ __launch_bounds__(256) void nodeout_kernel(
    const float* __restrict__ WL0, const float* __restrict__ WL1,
    float* __restrict__ out) {
    extern __shared__ float smem[];
    float* sW0 = smem;            // 128x64
    float* sW1 = sW0 + 8192;      // 128x64
    float* sS  = sW1 + 8192;      // 16 x 128
    float* sV  = sS + 16 * 128;   // 16 x 384
    int tid = threadIdx.x;
    const float SC = 0.0055242717280199021f;  // 1/(sqrt(128)*16)
    for (int i = tid; i < 8192; i += 256) { sW0[i] = WL0[i] * SC; sW1[i] = WL1[i] * SC; }
    int ln = tid >> 4;
    int cg = tid & 15;
    const float4* w0v = (const float4*)sW0;
    const float4* w1v = (const float4*)sW1;
    const int ntiles = N_NODES / 16;
    for (int tile = blockIdx.x; tile < ntiles; tile += gridDim.x) {
        int nb = tile * 16;
        __syncthreads();
        {
            const float4* srcS = (const float4*)(g_msgs + (size_t)nb * 128);
            float4* dstS = (float4*)sS;
            for (int i = tid; i < 512; i += 256) dstS[i] = srcS[i];
            const float4* srcV = (const float4*)(g_msgv + (size_t)nb * 384);
            float4* dstV = (float4*)sV;
            for (int i = tid; i < 1536; i += 256) dstV[i] = srcV[i];
        }
        __syncthreads();
        const float* S = sS + ln * 128;
        const float* V = sV + ln * 384;
        float4 aS = make_float4(0.f, 0.f, 0.f, 0.f);
        float4 a0 = aS, a1 = aS, a2 = aS;
#pragma unroll 4
        for (int u = 0; u < 128; u++) {
            float4 w0 = w0v[u * 16 + cg];
            float4 w1 = w1v[u * 16 + cg];
            float s  = S[u];
            float v0 = V[u], v1 = V[128 + u], v2 = V[256 + u];
            aS.x += s * w0.x; aS.y += s * w0.y; aS.z += s * w0.z; aS.w += s * w0.w;
            a0.x += v0 * w1.x; a0.y += v0 * w1.y; a0.z += v0 * w1.z; a0.w += v0 * w1.w;
            a1.x += v1 * w1.x; a1.y += v1 * w1.y; a1.z += v1 * w1.z; a1.w += v1 * w1.w;
            a2.x += v2 * w1.x; a2.y += v2 * w1.y; a2.z += v2 * w1.z; a2.w += v2 * w1.w;
        }
        int n = nb + ln;
        float* o = out + (size_t)n * 256;
        *(float4*)(o + 4 * cg) = aS;
        float* vp = o + 64 + 12 * cg;
        ((float4*)vp)[0] = make_float4(a0.x, a1.x, a2.x, a0.y);
        ((float4*)vp)[1] = make_float4(a1.y, a2.y, a0.z, a1.z);
        ((float4*)vp)[2] = make_float4(a2.z, a0.w, a1.w, a2.w);
    }
}

// ---------------------------------------------------------------------------
extern "C" void kernel_launch(void* const* d_in, const int* in_sizes, int n_in,
                              void* d_out, int out_size) {
    const float* node_feats = (const float*)d_in[1];
    const float* edge_attrs = (const float*)d_in[2];
    const float* edge_feats = (const float*)d_in[3];
    const int*   eidx       = (const int*)d_in[4];
    const float* W_up0      = (const float*)d_in[5];
    const float* W_up1      = (const float*)d_in[6];
    const float* M1         = (const float*)d_in[7];
    const float* M2         = (const float*)d_in[8];
    const float* M3         = (const float*)d_in[9];
    const float* M4         = (const float*)d_in[10];
    const float* WL0        = (const float*)d_in[11];
    const float* WL1        = (const float*)d_in[12];
    float* out = (float*)d_out;

    cudaFuncSetAttribute(edge_kernel,
                         cudaFuncAttributeMaxDynamicSharedMemorySize, EDGE_SMEM);
    cudaFuncSetAttribute(nodeout_kernel,
                         cudaFuncAttributeMaxDynamicSharedMemorySize, NODEOUT_SMEM);
    cudaFuncSetAttribute(nodeup_kernel,
                         cudaFuncAttributeMaxDynamicSharedMemorySize, NUP_SMEM);

    zero_kernel<<<256, 256>>>();
    nodeup_kernel<<<296, 256, NUP_SMEM>>>(node_feats, W_up0, W_up1);
    edge_kernel<<<296, 256, EDGE_SMEM>>>(edge_attrs, edge_feats,
                                         eidx, eidx + N_EDGES, M1, M2, M3, M4);
    nodeout_kernel<<<296, 256, NODEOUT_SMEM>>>(WL0, WL1, out);
}